// round 13
// baseline (speedup 1.0000x reference)
#include <cuda_runtime.h>
#include <cuda_bf16.h>
#include <cstdint>
#include <math.h>

// ---------------------------------------------------------------------------
// Problem constants
// ---------------------------------------------------------------------------
#define M_TOK 4096
#define HID   1024
#define NEXP  8
#define CAP   1536
static const size_t D_SZ = (size_t)M_TOK * NEXP * CAP;   // 50,331,648 per tensor

// GEMM tiling: single fused pass over K=1024, 4 tiles (Ah,Al,Bh,Bl) per stage
#define BM 128
#define BN 128
#define BK 64
#define NITER (HID / BK)                // 16
#define PITCHB 144                      // smem row pitch in BYTES
#define TILE_BYTES (128 * PITCHB)       // 18432
#define STAGE_BYTES (4 * TILE_BYTES)    // 73728 (Ah, Al, Bh, Bl)
#define SMEM_TOTAL (2 * STAGE_BYTES)    // 147456 -> occupancy 1

// ---------------------------------------------------------------------------
// Device scratch
// ---------------------------------------------------------------------------
__device__ float g_h[(size_t)M_TOK * HID];                        // 16 MB
__device__ __align__(16) __nv_bfloat16 g_Ah[(size_t)M_TOK * HID]; // 8 MB
__device__ __align__(16) __nv_bfloat16 g_Al[(size_t)M_TOK * HID]; // 8 MB
__device__ __align__(16) __nv_bfloat16 g_Bh[(size_t)HID * HID];   // 2 MB
__device__ __align__(16) __nv_bfloat16 g_Bl[(size_t)HID * HID];   // 2 MB
__device__ __align__(16) float g_paux[64 * NEXP];                 // prob sums

// ---------------------------------------------------------------------------
// PTX helpers
// ---------------------------------------------------------------------------
__device__ __forceinline__ uint32_t smem_u32(const void* p) {
    uint32_t a;
    asm("{ .reg .u64 t; cvta.to.shared.u64 t, %1; cvt.u32.u64 %0, t; }"
        : "=r"(a) : "l"(p));
    return a;
}
__device__ __forceinline__ void cp16(uint32_t dst, const void* src) {
    asm volatile("cp.async.cg.shared.global [%0], [%1], 16;"
                 :: "r"(dst), "l"(src) : "memory");
}
__device__ __forceinline__ void cp_commit() {
    asm volatile("cp.async.commit_group;" ::: "memory");
}
__device__ __forceinline__ void cp_wait1() {
    asm volatile("cp.async.wait_group 1;" ::: "memory");
}
__device__ __forceinline__ void ldsm_x4(uint32_t& r0, uint32_t& r1,
                                        uint32_t& r2, uint32_t& r3, uint32_t a) {
    asm volatile("ldmatrix.sync.aligned.m8n8.x4.shared.b16 {%0,%1,%2,%3}, [%4];"
                 : "=r"(r0), "=r"(r1), "=r"(r2), "=r"(r3) : "r"(a));
}
__device__ __forceinline__ void mma16816(float* c, const uint32_t* a,
                                         const uint32_t* b) {
    asm volatile(
        "mma.sync.aligned.m16n8k16.row.col.f32.bf16.bf16.f32 "
        "{%0,%1,%2,%3}, {%4,%5,%6,%7}, {%8,%9}, {%0,%1,%2,%3};"
        : "+f"(c[0]), "+f"(c[1]), "+f"(c[2]), "+f"(c[3])
        : "r"(a[0]), "r"(a[1]), "r"(a[2]), "r"(a[3]), "r"(b[0]), "r"(b[1]));
}

// ---------------------------------------------------------------------------
// Dummy kernel: pads launch sequence so ncu (index 3) captures the GEMM.
// ---------------------------------------------------------------------------
__global__ void dummy_kernel() {}

// ---------------------------------------------------------------------------
// Split fp32 -> bf16 hi + lo (row-major); also zeroes g_paux.
// ---------------------------------------------------------------------------
__global__ void split_kernel(const float* __restrict__ x,
                             const float* __restrict__ w1) {
    uint32_t g = blockIdx.x * blockDim.x + threadIdx.x;   // 0..655359
    if (g < 128) ((float4*)g_paux)[g] = make_float4(0.f, 0.f, 0.f, 0.f);

    const uint32_t NA = (M_TOK * HID) / 8;                // 524288
    bool isA = g < NA;
    uint32_t gb = isA ? g : g - NA;
    const float* src = (isA ? x : w1) + (size_t)gb * 8;

    float4 v0 = *(const float4*)src;
    float4 v1 = *(const float4*)(src + 4);
    float f[8] = {v0.x, v0.y, v0.z, v0.w, v1.x, v1.y, v1.z, v1.w};

    uint32_t H[4], L[4];
#pragma unroll
    for (int i = 0; i < 4; i++) {
        __nv_bfloat16 h0 = __float2bfloat16(f[2*i]);
        __nv_bfloat16 h1 = __float2bfloat16(f[2*i+1]);
        __nv_bfloat16 l0 = __float2bfloat16(f[2*i]   - __bfloat162float(h0));
        __nv_bfloat16 l1 = __float2bfloat16(f[2*i+1] - __bfloat162float(h1));
        H[i] = (uint32_t)__bfloat16_as_ushort(h0) |
               ((uint32_t)__bfloat16_as_ushort(h1) << 16);
        L[i] = (uint32_t)__bfloat16_as_ushort(l0) |
               ((uint32_t)__bfloat16_as_ushort(l1) << 16);
    }
    if (isA) {
        *(uint4*)&g_Ah[(size_t)gb * 8] = make_uint4(H[0], H[1], H[2], H[3]);
        *(uint4*)&g_Al[(size_t)gb * 8] = make_uint4(L[0], L[1], L[2], L[3]);
    } else {
        *(uint4*)&g_Bh[(size_t)gb * 8] = make_uint4(H[0], H[1], H[2], H[3]);
        *(uint4*)&g_Bl[(size_t)gb * 8] = make_uint4(L[0], L[1], L[2], L[3]);
    }
}

// ---------------------------------------------------------------------------
// Fused single-pass HMMA GEMM: C = Ah*Bh + Ah*Bl + Al*Bh (+bias, relu) -> g_h
// plus interleaved zero-fill of out. 16 iterations over K=1024; each stage
// holds Ah/Al/Bh/Bl tiles so every fragment load feeds 3 MMAs (1.5x reuse).
// 2-stage pipeline, 256 threads, 8 warps of 64x32, occupancy 1.
// ---------------------------------------------------------------------------
__global__ __launch_bounds__(256, 1)
void gemm_fused_kernel(const float* __restrict__ bias, float* __restrict__ out) {
    extern __shared__ __align__(128) unsigned char smem[];
    const uint32_t sb = smem_u32(smem);

    const int tid  = threadIdx.x;
    const int wid  = tid >> 5;
    const int lane = tid & 31;
    const int nb = blockIdx.x;
    const int mb = blockIdx.y;
    const int wm = wid >> 2;        // 0..1
    const int wn = wid & 3;         // 0..3

    float acc[4][4][4];
#pragma unroll
    for (int i = 0; i < 4; i++)
#pragma unroll
        for (int j = 0; j < 4; j++)
#pragma unroll
            for (int k = 0; k < 4; k++) acc[i][j][k] = 0.f;

    // stage layout: [Ah | Al | Bh | Bl], each 128 rows x 64 bf16 @144B pitch
    auto issue_stage = [&](int kt_idx) {
        int kbase = kt_idx * BK;
        uint32_t st = sb + (kt_idx & 1) * STAGE_BYTES;
#pragma unroll
        for (int it = 0; it < 4; it++) {
            int idx = tid + it * 256;       // 0..1023
            int row = idx >> 3;             // 0..127
            int ch  = idx & 7;              // 16B chunk
            uint32_t doff = row * PITCHB + ch * 16;
            size_t aoff = (size_t)(mb * BM + row) * HID + kbase + ch * 8;
            size_t boff = (size_t)(nb * BN + row) * HID + kbase + ch * 8;
            cp16(st + doff,                  g_Ah + aoff);
            cp16(st + TILE_BYTES + doff,     g_Al + aoff);
            cp16(st + 2 * TILE_BYTES + doff, g_Bh + boff);
            cp16(st + 3 * TILE_BYTES + doff, g_Bl + boff);
        }
    };

    issue_stage(0); cp_commit();
    issue_stage(1); cp_commit();

    const uint32_t gtid = (uint32_t)(mb * 8 + nb) * 256u + tid;
    float4* o4 = (float4*)out;
    const float4 zf = make_float4(0.f, 0.f, 0.f, 0.f);

    const uint32_t a_lrow = wm * 64 + (lane & 15);
    const uint32_t a_lcol = (lane >> 4) * 8;
    const uint32_t b_q = lane >> 3, b_r = lane & 7;
    const uint32_t b_nloc = wn * 32 + (b_q >> 1) * 8 + b_r;
    const uint32_t b_kloc = (b_q & 1) * 8;

    for (int i = 0; i < NITER; i++) {
        cp_wait1();
        __syncthreads();

        uint32_t stA = sb + (i & 1) * STAGE_BYTES;           // Ah
        uint32_t stAl = stA + TILE_BYTES;                     // Al
        uint32_t stBh = stA + 2 * TILE_BYTES;                 // Bh
        uint32_t stBl = stA + 3 * TILE_BYTES;                 // Bl

#pragma unroll
        for (int kt = 0; kt < 4; kt++) {
            // A fragments (hi and lo)
            uint32_t ah[4][4], al[4][4];
#pragma unroll
            for (int mt = 0; mt < 4; mt++) {
                uint32_t roff = (mt * 16 + a_lrow) * PITCHB + (kt * 16 + a_lcol) * 2;
                ldsm_x4(ah[mt][0], ah[mt][1], ah[mt][2], ah[mt][3], stA + roff);
                ldsm_x4(al[mt][0], al[mt][1], al[mt][2], al[mt][3], stAl + roff);
            }
            // B fragments (hi and lo)
            uint32_t bh[4][2], bl[4][2];
#pragma unroll
            for (int g = 0; g < 2; g++) {
                uint32_t roff = (b_nloc + g * 16) * PITCHB + (kt * 16 + b_kloc) * 2;
                uint32_t r0, r1, r2, r3;
                ldsm_x4(r0, r1, r2, r3, stBh + roff);
                bh[g * 2 + 0][0] = r0; bh[g * 2 + 0][1] = r1;
                bh[g * 2 + 1][0] = r2; bh[g * 2 + 1][1] = r3;
                ldsm_x4(r0, r1, r2, r3, stBl + roff);
                bl[g * 2 + 0][0] = r0; bl[g * 2 + 0][1] = r1;
                bl[g * 2 + 1][0] = r2; bl[g * 2 + 1][1] = r3;
            }
            // 3 fused terms per fragment pair
#pragma unroll
            for (int mt = 0; mt < 4; mt++)
#pragma unroll
                for (int nt = 0; nt < 4; nt++) {
                    mma16816(acc[mt][nt], ah[mt], bh[nt]);   // Ah*Bh
                    mma16816(acc[mt][nt], ah[mt], bl[nt]);   // Ah*Bl
                    mma16816(acc[mt][nt], al[mt], bh[nt]);   // Al*Bh
                }

            // spread zero-fill: 6 float4 per kt (24 per iteration)
#pragma unroll
            for (int j = 0; j < 6; j++)
                o4[(size_t)(i * 24 + kt * 6 + j) * 65536u + gtid] = zf;
        }

        __syncthreads();   // all warps done with slot before refill
        if (i + 2 < NITER) { issue_stage(i + 2); }
        cp_commit();
    }

    // epilogue: bias + relu -> g_h
    const int row_base = mb * BM + wm * 64 + (lane >> 2);
    const int col_base = nb * BN + wn * 32 + (lane & 3) * 2;
#pragma unroll
    for (int nt = 0; nt < 4; nt++) {
        int c = col_base + nt * 8;
        float b0 = __ldg(&bias[c]), b1 = __ldg(&bias[c + 1]);
#pragma unroll
        for (int mt = 0; mt < 4; mt++) {
            int r = row_base + mt * 16;
            float2 v0, v1;
            v0.x = fmaxf(acc[mt][nt][0] + b0, 0.f);
            v0.y = fmaxf(acc[mt][nt][1] + b1, 0.f);
            v1.x = fmaxf(acc[mt][nt][2] + b0, 0.f);
            v1.y = fmaxf(acc[mt][nt][3] + b1, 0.f);
            *(float2*)&g_h[(size_t)r * HID + c]       = v0;
            *(float2*)&g_h[(size_t)(r + 8) * HID + c] = v1;
        }
    }
}

// ---------------------------------------------------------------------------
// Router: per-token logits, softmax, top-2 scatter, router_probs.
// (exact R8 champion version; grid 4096 for latency hiding)
// ---------------------------------------------------------------------------
__global__ void router_kernel(const float* __restrict__ w2,
                              const float* __restrict__ b2,
                              float* __restrict__ out) {
    const int m   = blockIdx.x;
    const int tid = threadIdx.x;

    __shared__ __align__(16) float hs[HID];
    __shared__ float logits[NEXP];

    const float4* hrow = (const float4*)&g_h[(size_t)m * HID];
    ((float4*)hs)[tid] = hrow[tid];
    __syncthreads();

    const int e    = tid >> 5;
    const int lane = tid & 31;
    const float4* w2row = (const float4*)&w2[(size_t)e * HID];
    const float4* hs4   = (const float4*)hs;

    float sum = 0.f;
#pragma unroll
    for (int i = 0; i < 8; i++) {
        float4 a = hs4[lane + i * 32];
        float4 b = w2row[lane + i * 32];
        sum += a.x * b.x + a.y * b.y + a.z * b.z + a.w * b.w;
    }
#pragma unroll
    for (int off = 16; off > 0; off >>= 1)
        sum += __shfl_xor_sync(0xFFFFFFFFu, sum, off);
    if (lane == 0) logits[e] = sum + b2[e];
    __syncthreads();

    if (tid == 0) {
        float l[NEXP], p[NEXP];
        float mx = -1e30f;
#pragma unroll
        for (int i = 0; i < NEXP; i++) { l[i] = logits[i]; mx = fmaxf(mx, l[i]); }
        float s = 0.f;
#pragma unroll
        for (int i = 0; i < NEXP; i++) { p[i] = expf(l[i] - mx); s += p[i]; }
        float inv = 1.f / s;
#pragma unroll
        for (int i = 0; i < NEXP; i++) p[i] *= inv;

        float* rp = out + 2 * D_SZ + (size_t)m * NEXP;
        *(float4*)rp       = make_float4(p[0], p[1], p[2], p[3]);
        *(float4*)(rp + 4) = make_float4(p[4], p[5], p[6], p[7]);

        // prob sums for aux loss, spread over 64 buckets
        float* pa = &g_paux[(m & 63) * NEXP];
#pragma unroll
        for (int i = 0; i < NEXP; i++) atomicAdd(&pa[i], p[i]);

        int i1 = 0;
#pragma unroll
        for (int i = 1; i < NEXP; i++) if (p[i] > p[i1]) i1 = i;
        int i2 = -1;
#pragma unroll
        for (int i = 0; i < NEXP; i++) {
            if (i == i1) continue;
            if (i2 < 0 || p[i] > p[i2]) i2 = i;
        }
        float denom = p[i1] + p[i2];

        size_t base = (size_t)m * NEXP * CAP;
        out[base + (size_t)i1 * CAP] = 1.0f;
        out[base + (size_t)i2 * CAP] = 1.0f;
        out[D_SZ + base + (size_t)i1 * CAP] = p[i1] / denom;
        out[D_SZ + base + (size_t)i2 * CAP] = p[i2] / denom;
    }
}

// ---------------------------------------------------------------------------
// Aux finalize: reduce g_paux[64][8] -> aux loss scalar.
// ---------------------------------------------------------------------------
__global__ void aux_final_kernel(float* __restrict__ out) {
    __shared__ float s[NEXP][64];
    int tid = threadIdx.x;   // 64 threads
    float4 a = ((const float4*)g_paux)[tid * 2];
    float4 b = ((const float4*)g_paux)[tid * 2 + 1];
    s[0][tid] = a.x; s[1][tid] = a.y; s[2][tid] = a.z; s[3][tid] = a.w;
    s[4][tid] = b.x; s[5][tid] = b.y; s[6][tid] = b.z; s[7][tid] = b.w;
    __syncthreads();
    for (int str = 32; str > 0; str >>= 1) {
        if (tid < str) {
#pragma unroll
            for (int e = 0; e < NEXP; e++) s[e][tid] += s[e][tid + str];
        }
        __syncthreads();
    }
    if (tid == 0) {
        float aux = 0.f;
#pragma unroll
        for (int i = 0; i < NEXP; i++) {
            float mean = s[i][0] / (float)M_TOK;
            aux += mean * logf(mean * (float)NEXP + 1e-9f);
        }
        out[2 * D_SZ + (size_t)M_TOK * NEXP] = aux;
    }
}

// ---------------------------------------------------------------------------
extern "C" void kernel_launch(void* const* d_in, const int* in_sizes, int n_in,
                              void* d_out, int out_size)
{
    const float* x  = (const float*)d_in[0];
    const float* w1 = (const float*)d_in[1];
    const float* b1 = (const float*)d_in[2];
    const float* w2 = (const float*)d_in[3];
    const float* b2 = (const float*)d_in[4];
    float* out = (float*)d_out;

    cudaFuncSetAttribute(gemm_fused_kernel,
                         cudaFuncAttributeMaxDynamicSharedMemorySize, SMEM_TOTAL);

    // launch 0: split fp32 -> bf16 hi/lo (+ zero g_paux)
    split_kernel<<<2560, 256>>>(x, w1);

    // launches 1,2: padding so ncu (index 3) profiles the fused GEMM
    dummy_kernel<<<1, 32>>>();
    dummy_kernel<<<1, 32>>>();

    // launch 3: fused single-pass GEMM (+bias+ReLU -> g_h) + zero-fill of out
    dim3 grid(HID / BN, M_TOK / BM);   // (8, 32)
    gemm_fused_kernel<<<grid, 256, SMEM_TOTAL>>>(b1, out);

    // launch 4: router (+ prob-sum atomics)
    router_kernel<<<M_TOK, 256>>>(w2, b2, out);

    // launch 5: aux finalize
    aux_final_kernel<<<1, 64>>>(out);
}

// round 14
// speedup vs baseline: 1.0499x; 1.0499x over previous
#include <cuda_runtime.h>
#include <cuda_bf16.h>
#include <cstdint>
#include <math.h>

// ---------------------------------------------------------------------------
// Problem constants
// ---------------------------------------------------------------------------
#define M_TOK 4096
#define HID   1024
#define NEXP  8
#define CAP   1536
static const size_t D_SZ = (size_t)M_TOK * NEXP * CAP;   // 50,331,648 per tensor

// GEMM tiling (R8 champion structure)
#define BM 128
#define BN 128
#define BK 64
#define KTOT 3072
#define NITER (KTOT / BK)               // 48
#define PITCHB 144                      // smem row pitch in BYTES
#define TILE_BYTES (128 * PITCHB)       // 18432
#define STAGE_BYTES (2 * TILE_BYTES)    // 36864
#define ZBUF_BYTES 2048                 // bulk zero source buffer
#define SMEM_TOTAL (3 * STAGE_BYTES + ZBUF_BYTES)   // 112640 (x2 = 225280 <= 228K)

// zero-fill via bulk engine: 256 CTAs x 768 chunks x 2KB = 402,653,184 B
#define ZCHUNKS_PER_CTA 768
#define ZCHUNKS_PER_ITER 16             // 768 / 48

// ---------------------------------------------------------------------------
// Device scratch
// ---------------------------------------------------------------------------
__device__ float g_h[(size_t)M_TOK * HID];                        // 16 MB
__device__ __align__(16) __nv_bfloat16 g_Ah[(size_t)M_TOK * HID]; // 8 MB
__device__ __align__(16) __nv_bfloat16 g_Al[(size_t)M_TOK * HID]; // 8 MB
__device__ __align__(16) __nv_bfloat16 g_Bh[(size_t)HID * HID];   // 2 MB
__device__ __align__(16) __nv_bfloat16 g_Bl[(size_t)HID * HID];   // 2 MB
__device__ __align__(16) float g_paux[64 * NEXP];                 // prob sums

// ---------------------------------------------------------------------------
// PTX helpers
// ---------------------------------------------------------------------------
__device__ __forceinline__ uint32_t smem_u32(const void* p) {
    uint32_t a;
    asm("{ .reg .u64 t; cvta.to.shared.u64 t, %1; cvt.u32.u64 %0, t; }"
        : "=r"(a) : "l"(p));
    return a;
}
__device__ __forceinline__ void cp16(uint32_t dst, const void* src) {
    asm volatile("cp.async.cg.shared.global [%0], [%1], 16;"
                 :: "r"(dst), "l"(src) : "memory");
}
__device__ __forceinline__ void cp_commit() {
    asm volatile("cp.async.commit_group;" ::: "memory");
}
__device__ __forceinline__ void cp_wait1() {
    asm volatile("cp.async.wait_group 1;" ::: "memory");
}
__device__ __forceinline__ void ldsm_x4(uint32_t& r0, uint32_t& r1,
                                        uint32_t& r2, uint32_t& r3, uint32_t a) {
    asm volatile("ldmatrix.sync.aligned.m8n8.x4.shared.b16 {%0,%1,%2,%3}, [%4];"
                 : "=r"(r0), "=r"(r1), "=r"(r2), "=r"(r3) : "r"(a));
}
__device__ __forceinline__ void mma16816(float* c, const uint32_t* a,
                                         const uint32_t* b) {
    asm volatile(
        "mma.sync.aligned.m16n8k16.row.col.f32.bf16.bf16.f32 "
        "{%0,%1,%2,%3}, {%4,%5,%6,%7}, {%8,%9}, {%0,%1,%2,%3};"
        : "+f"(c[0]), "+f"(c[1]), "+f"(c[2]), "+f"(c[3])
        : "r"(a[0]), "r"(a[1]), "r"(a[2]), "r"(a[3]), "r"(b[0]), "r"(b[1]));
}
// bulk S2G zero store (2KB chunk) -- rides the async engine, not the LSU
__device__ __forceinline__ void bulk_s2g(void* dst, uint32_t src_smem) {
    asm volatile("cp.async.bulk.global.shared::cta.bulk_group [%0], [%1], %2;"
                 :: "l"(dst), "r"(src_smem), "n"(ZBUF_BYTES) : "memory");
}
__device__ __forceinline__ void bulk_commit() {
    asm volatile("cp.async.bulk.commit_group;" ::: "memory");
}
__device__ __forceinline__ void bulk_wait0() {
    asm volatile("cp.async.bulk.wait_group 0;" ::: "memory");
}

// ---------------------------------------------------------------------------
// Dummy kernel: pads launch sequence so ncu (index 3) captures the GEMM.
// ---------------------------------------------------------------------------
__global__ void dummy_kernel() {}

// ---------------------------------------------------------------------------
// Split fp32 -> bf16 hi + lo (row-major); also zeroes g_paux.
// ---------------------------------------------------------------------------
__global__ void split_kernel(const float* __restrict__ x,
                             const float* __restrict__ w1) {
    uint32_t g = blockIdx.x * blockDim.x + threadIdx.x;   // 0..655359
    if (g < 128) ((float4*)g_paux)[g] = make_float4(0.f, 0.f, 0.f, 0.f);

    const uint32_t NA = (M_TOK * HID) / 8;                // 524288
    bool isA = g < NA;
    uint32_t gb = isA ? g : g - NA;
    const float* src = (isA ? x : w1) + (size_t)gb * 8;

    float4 v0 = *(const float4*)src;
    float4 v1 = *(const float4*)(src + 4);
    float f[8] = {v0.x, v0.y, v0.z, v0.w, v1.x, v1.y, v1.z, v1.w};

    uint32_t H[4], L[4];
#pragma unroll
    for (int i = 0; i < 4; i++) {
        __nv_bfloat16 h0 = __float2bfloat16(f[2*i]);
        __nv_bfloat16 h1 = __float2bfloat16(f[2*i+1]);
        __nv_bfloat16 l0 = __float2bfloat16(f[2*i]   - __bfloat162float(h0));
        __nv_bfloat16 l1 = __float2bfloat16(f[2*i+1] - __bfloat162float(h1));
        H[i] = (uint32_t)__bfloat16_as_ushort(h0) |
               ((uint32_t)__bfloat16_as_ushort(h1) << 16);
        L[i] = (uint32_t)__bfloat16_as_ushort(l0) |
               ((uint32_t)__bfloat16_as_ushort(l1) << 16);
    }
    if (isA) {
        *(uint4*)&g_Ah[(size_t)gb * 8] = make_uint4(H[0], H[1], H[2], H[3]);
        *(uint4*)&g_Al[(size_t)gb * 8] = make_uint4(L[0], L[1], L[2], L[3]);
    } else {
        *(uint4*)&g_Bh[(size_t)gb * 8] = make_uint4(H[0], H[1], H[2], H[3]);
        *(uint4*)&g_Bl[(size_t)gb * 8] = make_uint4(L[0], L[1], L[2], L[3]);
    }
}

// ---------------------------------------------------------------------------
// Fused HMMA GEMM (3-term bf16 split, BK=64) + bulk-engine zero-fill.
// Main loop identical to R8 champion; zero stores moved off the LSU:
// tid 0 issues 16 x 2KB cp.async.bulk S2G per iteration (no wait in loop;
// single drain after the epilogue).
// ---------------------------------------------------------------------------
__global__ __launch_bounds__(256, 2)
void gemm_fused_kernel(const float* __restrict__ bias, float* __restrict__ out) {
    extern __shared__ __align__(128) unsigned char smem[];
    const uint32_t sb = smem_u32(smem);
    const uint32_t zb = sb + 3 * STAGE_BYTES;

    const int tid  = threadIdx.x;
    const int wid  = tid >> 5;
    const int lane = tid & 31;
    const int nb = blockIdx.x;
    const int mb = blockIdx.y;
    const int wm = wid >> 2;
    const int wn = wid & 3;

    // zero the bulk source buffer (first 128 threads x 16B = 2KB)
    if (tid < 128)
        *(float4*)(smem + 3 * STAGE_BYTES + tid * 16) =
            make_float4(0.f, 0.f, 0.f, 0.f);

    float acc[4][4][4];
#pragma unroll
    for (int i = 0; i < 4; i++)
#pragma unroll
        for (int j = 0; j < 4; j++)
#pragma unroll
            for (int k = 0; k < 4; k++) acc[i][j][k] = 0.f;

    auto issue_stage = [&](int kt_idx) {
        int kk = kt_idx * BK;               // global k in [0, 3072)
        int p  = kk >> 10;
        int kbase = kk & 1023;
        const __nv_bfloat16* sA = (p < 2) ? g_Ah : g_Al;
        const __nv_bfloat16* sB = (p == 1) ? g_Bl : g_Bh;
        uint32_t st = sb + (kt_idx % 3) * STAGE_BYTES;
#pragma unroll
        for (int it = 0; it < 4; it++) {
            int idx = tid + it * 256;       // 0..1023
            int row = idx >> 3;             // 0..127
            int ch  = idx & 7;              // 0..7 (16B chunks)
            cp16(st + row * PITCHB + ch * 16,
                 sA + (size_t)(mb * BM + row) * HID + kbase + ch * 8);
            cp16(st + TILE_BYTES + row * PITCHB + ch * 16,
                 sB + (size_t)(nb * BN + row) * HID + kbase + ch * 8);
        }
    };

    issue_stage(0); cp_commit();
    issue_stage(1); cp_commit();

    // make zero buffer visible to the async (bulk) proxy
    __syncthreads();
    asm volatile("fence.proxy.async.shared::cta;" ::: "memory");

    // this CTA's contiguous zero region: 768 x 2KB
    unsigned char* zdst = (unsigned char*)out
                        + (size_t)(mb * 8 + nb) * ZCHUNKS_PER_CTA * ZBUF_BYTES;

    const uint32_t a_lrow = wm * 64 + (lane & 15);
    const uint32_t a_lcol = (lane >> 4) * 8;
    const uint32_t b_q = lane >> 3, b_r = lane & 7;
    const uint32_t b_nloc = wn * 32 + (b_q >> 1) * 8 + b_r;
    const uint32_t b_kloc = (b_q & 1) * 8;

    for (int i = 0; i < NITER; i++) {
        cp_wait1();
        __syncthreads();

        if (i + 2 < NITER) issue_stage(i + 2);
        cp_commit();

        // bulk zero-fill: 16 x 2KB per iteration from one thread; NO wait here
        if (tid == 0) {
#pragma unroll
            for (int j = 0; j < ZCHUNKS_PER_ITER; j++)
                bulk_s2g(zdst + (size_t)(i * ZCHUNKS_PER_ITER + j) * ZBUF_BYTES, zb);
            bulk_commit();
        }

        uint32_t stA = sb + (i % 3) * STAGE_BYTES;
        uint32_t stB = stA + TILE_BYTES;

#pragma unroll
        for (int kt = 0; kt < 4; kt++) {
            uint32_t af[4][4];
#pragma unroll
            for (int mt = 0; mt < 4; mt++) {
                uint32_t addr = stA + (mt * 16 + a_lrow) * PITCHB
                              + (kt * 16 + a_lcol) * 2;
                ldsm_x4(af[mt][0], af[mt][1], af[mt][2], af[mt][3], addr);
            }
            uint32_t bf[4][2];
#pragma unroll
            for (int g = 0; g < 2; g++) {
                uint32_t addr = stB + (b_nloc + g * 16) * PITCHB
                              + (kt * 16 + b_kloc) * 2;
                uint32_t r0, r1, r2, r3;
                ldsm_x4(r0, r1, r2, r3, addr);
                bf[g * 2 + 0][0] = r0; bf[g * 2 + 0][1] = r1;
                bf[g * 2 + 1][0] = r2; bf[g * 2 + 1][1] = r3;
            }
#pragma unroll
            for (int mt = 0; mt < 4; mt++)
#pragma unroll
                for (int nt = 0; nt < 4; nt++)
                    mma16816(acc[mt][nt], af[mt], bf[nt]);
        }
    }

    // epilogue: bias + relu -> g_h
    const int row_base = mb * BM + wm * 64 + (lane >> 2);
    const int col_base = nb * BN + wn * 32 + (lane & 3) * 2;
#pragma unroll
    for (int nt = 0; nt < 4; nt++) {
        int c = col_base + nt * 8;
        float b0 = __ldg(&bias[c]), b1 = __ldg(&bias[c + 1]);
#pragma unroll
        for (int mt = 0; mt < 4; mt++) {
            int r = row_base + mt * 16;
            float2 v0, v1;
            v0.x = fmaxf(acc[mt][nt][0] + b0, 0.f);
            v0.y = fmaxf(acc[mt][nt][1] + b1, 0.f);
            v1.x = fmaxf(acc[mt][nt][2] + b0, 0.f);
            v1.y = fmaxf(acc[mt][nt][3] + b1, 0.f);
            *(float2*)&g_h[(size_t)r * HID + c]       = v0;
            *(float2*)&g_h[(size_t)(r + 8) * HID + c] = v1;
        }
    }

    // single drain of all bulk zero stores
    if (tid == 0) bulk_wait0();
}

// ---------------------------------------------------------------------------
// Router: per-token logits, softmax, top-2 scatter, router_probs.
// (exact R8 champion version; grid 4096, + prob-sum atomics for aux)
// ---------------------------------------------------------------------------
__global__ void router_kernel(const float* __restrict__ w2,
                              const float* __restrict__ b2,
                              float* __restrict__ out) {
    const int m   = blockIdx.x;
    const int tid = threadIdx.x;

    __shared__ __align__(16) float hs[HID];
    __shared__ float logits[NEXP];

    const float4* hrow = (const float4*)&g_h[(size_t)m * HID];
    ((float4*)hs)[tid] = hrow[tid];
    __syncthreads();

    const int e    = tid >> 5;
    const int lane = tid & 31;
    const float4* w2row = (const float4*)&w2[(size_t)e * HID];
    const float4* hs4   = (const float4*)hs;

    float sum = 0.f;
#pragma unroll
    for (int i = 0; i < 8; i++) {
        float4 a = hs4[lane + i * 32];
        float4 b = w2row[lane + i * 32];
        sum += a.x * b.x + a.y * b.y + a.z * b.z + a.w * b.w;
    }
#pragma unroll
    for (int off = 16; off > 0; off >>= 1)
        sum += __shfl_xor_sync(0xFFFFFFFFu, sum, off);
    if (lane == 0) logits[e] = sum + b2[e];
    __syncthreads();

    if (tid == 0) {
        float l[NEXP], p[NEXP];
        float mx = -1e30f;
#pragma unroll
        for (int i = 0; i < NEXP; i++) { l[i] = logits[i]; mx = fmaxf(mx, l[i]); }
        float s = 0.f;
#pragma unroll
        for (int i = 0; i < NEXP; i++) { p[i] = expf(l[i] - mx); s += p[i]; }
        float inv = 1.f / s;
#pragma unroll
        for (int i = 0; i < NEXP; i++) p[i] *= inv;

        float* rp = out + 2 * D_SZ + (size_t)m * NEXP;
        *(float4*)rp       = make_float4(p[0], p[1], p[2], p[3]);
        *(float4*)(rp + 4) = make_float4(p[4], p[5], p[6], p[7]);

        // prob sums for aux loss, spread over 64 buckets
        float* pa = &g_paux[(m & 63) * NEXP];
#pragma unroll
        for (int i = 0; i < NEXP; i++) atomicAdd(&pa[i], p[i]);

        int i1 = 0;
#pragma unroll
        for (int i = 1; i < NEXP; i++) if (p[i] > p[i1]) i1 = i;
        int i2 = -1;
#pragma unroll
        for (int i = 0; i < NEXP; i++) {
            if (i == i1) continue;
            if (i2 < 0 || p[i] > p[i2]) i2 = i;
        }
        float denom = p[i1] + p[i2];

        size_t base = (size_t)m * NEXP * CAP;
        out[base + (size_t)i1 * CAP] = 1.0f;
        out[base + (size_t)i2 * CAP] = 1.0f;
        out[D_SZ + base + (size_t)i1 * CAP] = p[i1] / denom;
        out[D_SZ + base + (size_t)i2 * CAP] = p[i2] / denom;
    }
}

// ---------------------------------------------------------------------------
// Aux finalize: reduce g_paux[64][8] -> aux loss scalar.
// ---------------------------------------------------------------------------
__global__ void aux_final_kernel(float* __restrict__ out) {
    __shared__ float s[NEXP][64];
    int tid = threadIdx.x;   // 64 threads
    float4 a = ((const float4*)g_paux)[tid * 2];
    float4 b = ((const float4*)g_paux)[tid * 2 + 1];
    s[0][tid] = a.x; s[1][tid] = a.y; s[2][tid] = a.z; s[3][tid] = a.w;
    s[4][tid] = b.x; s[5][tid] = b.y; s[6][tid] = b.z; s[7][tid] = b.w;
    __syncthreads();
    for (int str = 32; str > 0; str >>= 1) {
        if (tid < str) {
#pragma unroll
            for (int e = 0; e < NEXP; e++) s[e][tid] += s[e][tid + str];
        }
        __syncthreads();
    }
    if (tid == 0) {
        float aux = 0.f;
#pragma unroll
        for (int i = 0; i < NEXP; i++) {
            float mean = s[i][0] / (float)M_TOK;
            aux += mean * logf(mean * (float)NEXP + 1e-9f);
        }
        out[2 * D_SZ + (size_t)M_TOK * NEXP] = aux;
    }
}

// ---------------------------------------------------------------------------
extern "C" void kernel_launch(void* const* d_in, const int* in_sizes, int n_in,
                              void* d_out, int out_size)
{
    const float* x  = (const float*)d_in[0];
    const float* w1 = (const float*)d_in[1];
    const float* b1 = (const float*)d_in[2];
    const float* w2 = (const float*)d_in[3];
    const float* b2 = (const float*)d_in[4];
    float* out = (float*)d_out;

    cudaFuncSetAttribute(gemm_fused_kernel,
                         cudaFuncAttributeMaxDynamicSharedMemorySize, SMEM_TOTAL);

    // launch 0: split fp32 -> bf16 hi/lo (+ zero g_paux)
    split_kernel<<<2560, 256>>>(x, w1);

    // launches 1,2: padding so ncu (index 3) profiles the GEMM
    dummy_kernel<<<1, 32>>>();
    dummy_kernel<<<1, 32>>>();

    // launch 3: fused GEMM (+bias+ReLU -> g_h) + bulk zero-fill of out
    dim3 grid(HID / BN, M_TOK / BM);   // (8, 32)
    gemm_fused_kernel<<<grid, 256, SMEM_TOTAL>>>(b1, out);

    // launch 4: router (+ prob-sum atomics)
    router_kernel<<<M_TOK, 256>>>(w2, b2, out);

    // launch 5: aux finalize
    aux_final_kernel<<<1, 64>>>(out);
}

// round 15
// speedup vs baseline: 1.0973x; 1.0452x over previous
#include <cuda_runtime.h>
#include <cuda_bf16.h>
#include <cstdint>
#include <math.h>

// ---------------------------------------------------------------------------
// Problem constants
// ---------------------------------------------------------------------------
#define M_TOK 4096
#define HID   1024
#define NEXP  8
#define CAP   1536
static const size_t D_SZ = (size_t)M_TOK * NEXP * CAP;   // 50,331,648 per tensor

// GEMM tiling (R8 champion structure, byte-identical main loop)
#define BM 128
#define BN 128
#define BK 64
#define KTOT 3072
#define NITER (KTOT / BK)               // 48
#define PITCHB 144                      // smem row pitch in BYTES
#define TILE_BYTES (128 * PITCHB)       // 18432
#define STAGE_BYTES (2 * TILE_BYTES)    // 36864
#define SMEM_TOTAL (3 * STAGE_BYTES)    // 110592

// ---------------------------------------------------------------------------
// Device scratch
// ---------------------------------------------------------------------------
__device__ float g_h[(size_t)M_TOK * HID];                        // 16 MB
__device__ __align__(16) __nv_bfloat16 g_Ah[(size_t)M_TOK * HID]; // 8 MB
__device__ __align__(16) __nv_bfloat16 g_Al[(size_t)M_TOK * HID]; // 8 MB
__device__ __align__(16) __nv_bfloat16 g_Bh[(size_t)HID * HID];   // 2 MB
__device__ __align__(16) __nv_bfloat16 g_Bl[(size_t)HID * HID];   // 2 MB
__device__ __align__(16) float g_paux[64 * NEXP];                 // prob sums
__device__ unsigned int g_done;                                   // router block counter

// ---------------------------------------------------------------------------
// PTX helpers
// ---------------------------------------------------------------------------
__device__ __forceinline__ uint32_t smem_u32(const void* p) {
    uint32_t a;
    asm("{ .reg .u64 t; cvta.to.shared.u64 t, %1; cvt.u32.u64 %0, t; }"
        : "=r"(a) : "l"(p));
    return a;
}
__device__ __forceinline__ void cp16(uint32_t dst, const void* src) {
    asm volatile("cp.async.cg.shared.global [%0], [%1], 16;"
                 :: "r"(dst), "l"(src) : "memory");
}
__device__ __forceinline__ void cp_commit() {
    asm volatile("cp.async.commit_group;" ::: "memory");
}
__device__ __forceinline__ void cp_wait1() {
    asm volatile("cp.async.wait_group 1;" ::: "memory");
}
__device__ __forceinline__ void ldsm_x4(uint32_t& r0, uint32_t& r1,
                                        uint32_t& r2, uint32_t& r3, uint32_t a) {
    asm volatile("ldmatrix.sync.aligned.m8n8.x4.shared.b16 {%0,%1,%2,%3}, [%4];"
                 : "=r"(r0), "=r"(r1), "=r"(r2), "=r"(r3) : "r"(a));
}
__device__ __forceinline__ void mma16816(float* c, const uint32_t* a,
                                         const uint32_t* b) {
    asm volatile(
        "mma.sync.aligned.m16n8k16.row.col.f32.bf16.bf16.f32 "
        "{%0,%1,%2,%3}, {%4,%5,%6,%7}, {%8,%9}, {%0,%1,%2,%3};"
        : "+f"(c[0]), "+f"(c[1]), "+f"(c[2]), "+f"(c[3])
        : "r"(a[0]), "r"(a[1]), "r"(a[2]), "r"(a[3]), "r"(b[0]), "r"(b[1]));
}

// ---------------------------------------------------------------------------
// Split fp32 -> bf16 hi + lo (row-major); also zeroes g_paux + g_done.
// ---------------------------------------------------------------------------
__global__ void split_kernel(const float* __restrict__ x,
                             const float* __restrict__ w1) {
    uint32_t g = blockIdx.x * blockDim.x + threadIdx.x;   // 0..655359
    if (g < 128) ((float4*)g_paux)[g] = make_float4(0.f, 0.f, 0.f, 0.f);
    if (g == 128) g_done = 0;

    const uint32_t NA = (M_TOK * HID) / 8;                // 524288
    bool isA = g < NA;
    uint32_t gb = isA ? g : g - NA;
    const float* src = (isA ? x : w1) + (size_t)gb * 8;

    float4 v0 = *(const float4*)src;
    float4 v1 = *(const float4*)(src + 4);
    float f[8] = {v0.x, v0.y, v0.z, v0.w, v1.x, v1.y, v1.z, v1.w};

    uint32_t H[4], L[4];
#pragma unroll
    for (int i = 0; i < 4; i++) {
        __nv_bfloat16 h0 = __float2bfloat16(f[2*i]);
        __nv_bfloat16 h1 = __float2bfloat16(f[2*i+1]);
        __nv_bfloat16 l0 = __float2bfloat16(f[2*i]   - __bfloat162float(h0));
        __nv_bfloat16 l1 = __float2bfloat16(f[2*i+1] - __bfloat162float(h1));
        H[i] = (uint32_t)__bfloat16_as_ushort(h0) |
               ((uint32_t)__bfloat16_as_ushort(h1) << 16);
        L[i] = (uint32_t)__bfloat16_as_ushort(l0) |
               ((uint32_t)__bfloat16_as_ushort(l1) << 16);
    }
    if (isA) {
        *(uint4*)&g_Ah[(size_t)gb * 8] = make_uint4(H[0], H[1], H[2], H[3]);
        *(uint4*)&g_Al[(size_t)gb * 8] = make_uint4(L[0], L[1], L[2], L[3]);
    } else {
        *(uint4*)&g_Bh[(size_t)gb * 8] = make_uint4(H[0], H[1], H[2], H[3]);
        *(uint4*)&g_Bl[(size_t)gb * 8] = make_uint4(L[0], L[1], L[2], L[3]);
    }
}

// ---------------------------------------------------------------------------
// Fused HMMA GEMM (3-term bf16 split, BK=64) + interleaved zero-fill.
// BYTE-IDENTICAL to the R8 champion (147.5 -> 141.8 winner, 114.4us).
// ---------------------------------------------------------------------------
__global__ __launch_bounds__(256, 2)
void gemm_fused_kernel(const float* __restrict__ bias, float* __restrict__ out) {
    extern __shared__ __align__(128) unsigned char smem[];
    const uint32_t sb = smem_u32(smem);

    const int tid  = threadIdx.x;
    const int wid  = tid >> 5;
    const int lane = tid & 31;
    const int nb = blockIdx.x;
    const int mb = blockIdx.y;
    const int wm = wid >> 2;
    const int wn = wid & 3;

    float acc[4][4][4];
#pragma unroll
    for (int i = 0; i < 4; i++)
#pragma unroll
        for (int j = 0; j < 4; j++)
#pragma unroll
            for (int k = 0; k < 4; k++) acc[i][j][k] = 0.f;

    auto issue_stage = [&](int kt_idx) {
        int kk = kt_idx * BK;               // global k in [0, 3072)
        int p  = kk >> 10;
        int kbase = kk & 1023;
        const __nv_bfloat16* sA = (p < 2) ? g_Ah : g_Al;
        const __nv_bfloat16* sB = (p == 1) ? g_Bl : g_Bh;
        uint32_t st = sb + (kt_idx % 3) * STAGE_BYTES;
#pragma unroll
        for (int it = 0; it < 4; it++) {
            int idx = tid + it * 256;       // 0..1023
            int row = idx >> 3;             // 0..127
            int ch  = idx & 7;              // 0..7 (16B chunks)
            cp16(st + row * PITCHB + ch * 16,
                 sA + (size_t)(mb * BM + row) * HID + kbase + ch * 8);
            cp16(st + TILE_BYTES + row * PITCHB + ch * 16,
                 sB + (size_t)(nb * BN + row) * HID + kbase + ch * 8);
        }
    };

    issue_stage(0); cp_commit();
    issue_stage(1); cp_commit();

    const uint32_t gtid = (uint32_t)(mb * 8 + nb) * 256u + tid;
    float4* o4 = (float4*)out;
    const float4 zf = make_float4(0.f, 0.f, 0.f, 0.f);

    const uint32_t a_lrow = wm * 64 + (lane & 15);
    const uint32_t a_lcol = (lane >> 4) * 8;
    const uint32_t b_q = lane >> 3, b_r = lane & 7;
    const uint32_t b_nloc = wn * 32 + (b_q >> 1) * 8 + b_r;
    const uint32_t b_kloc = (b_q & 1) * 8;

    for (int i = 0; i < NITER; i++) {
        cp_wait1();
        __syncthreads();

        if (i + 2 < NITER) issue_stage(i + 2);
        cp_commit();

        // interleaved zero-fill: 8 float4 per thread per iter
#pragma unroll
        for (int j = 0; j < 8; j++)
            o4[(size_t)(i * 8 + j) * 65536u + gtid] = zf;

        uint32_t stA = sb + (i % 3) * STAGE_BYTES;
        uint32_t stB = stA + TILE_BYTES;

#pragma unroll
        for (int kt = 0; kt < 4; kt++) {
            uint32_t af[4][4];
#pragma unroll
            for (int mt = 0; mt < 4; mt++) {
                uint32_t addr = stA + (mt * 16 + a_lrow) * PITCHB
                              + (kt * 16 + a_lcol) * 2;
                ldsm_x4(af[mt][0], af[mt][1], af[mt][2], af[mt][3], addr);
            }
            uint32_t bf[4][2];
#pragma unroll
            for (int g = 0; g < 2; g++) {
                uint32_t addr = stB + (b_nloc + g * 16) * PITCHB
                              + (kt * 16 + b_kloc) * 2;
                uint32_t r0, r1, r2, r3;
                ldsm_x4(r0, r1, r2, r3, addr);
                bf[g * 2 + 0][0] = r0; bf[g * 2 + 0][1] = r1;
                bf[g * 2 + 1][0] = r2; bf[g * 2 + 1][1] = r3;
            }
#pragma unroll
            for (int mt = 0; mt < 4; mt++)
#pragma unroll
                for (int nt = 0; nt < 4; nt++)
                    mma16816(acc[mt][nt], af[mt], bf[nt]);
        }
    }

    // epilogue: bias + relu -> g_h
    const int row_base = mb * BM + wm * 64 + (lane >> 2);
    const int col_base = nb * BN + wn * 32 + (lane & 3) * 2;
#pragma unroll
    for (int nt = 0; nt < 4; nt++) {
        int c = col_base + nt * 8;
        float b0 = __ldg(&bias[c]), b1 = __ldg(&bias[c + 1]);
#pragma unroll
        for (int mt = 0; mt < 4; mt++) {
            int r = row_base + mt * 16;
            float2 v0, v1;
            v0.x = fmaxf(acc[mt][nt][0] + b0, 0.f);
            v0.y = fmaxf(acc[mt][nt][1] + b1, 0.f);
            v1.x = fmaxf(acc[mt][nt][2] + b0, 0.f);
            v1.y = fmaxf(acc[mt][nt][3] + b1, 0.f);
            *(float2*)&g_h[(size_t)r * HID + c]       = v0;
            *(float2*)&g_h[(size_t)(r + 8) * HID + c] = v1;
        }
    }
}

// ---------------------------------------------------------------------------
// Router: per-token logits, softmax, top-2 scatter, router_probs
// + prob-sum atomics; the LAST block also reduces g_paux -> aux loss
// (saves the separate aux_final launch).
// ---------------------------------------------------------------------------
__global__ void router_kernel(const float* __restrict__ w2,
                              const float* __restrict__ b2,
                              float* __restrict__ out) {
    const int m   = blockIdx.x;
    const int tid = threadIdx.x;

    __shared__ __align__(16) float hs[HID];
    __shared__ float logits[NEXP];
    __shared__ unsigned int s_last;

    const float4* hrow = (const float4*)&g_h[(size_t)m * HID];
    ((float4*)hs)[tid] = hrow[tid];
    __syncthreads();

    const int e    = tid >> 5;
    const int lane = tid & 31;
    const float4* w2row = (const float4*)&w2[(size_t)e * HID];
    const float4* hs4   = (const float4*)hs;

    float sum = 0.f;
#pragma unroll
    for (int i = 0; i < 8; i++) {
        float4 a = hs4[lane + i * 32];
        float4 b = w2row[lane + i * 32];
        sum += a.x * b.x + a.y * b.y + a.z * b.z + a.w * b.w;
    }
#pragma unroll
    for (int off = 16; off > 0; off >>= 1)
        sum += __shfl_xor_sync(0xFFFFFFFFu, sum, off);
    if (lane == 0) logits[e] = sum + b2[e];
    __syncthreads();

    if (tid == 0) {
        float l[NEXP], p[NEXP];
        float mx = -1e30f;
#pragma unroll
        for (int i = 0; i < NEXP; i++) { l[i] = logits[i]; mx = fmaxf(mx, l[i]); }
        float s = 0.f;
#pragma unroll
        for (int i = 0; i < NEXP; i++) { p[i] = expf(l[i] - mx); s += p[i]; }
        float inv = 1.f / s;
#pragma unroll
        for (int i = 0; i < NEXP; i++) p[i] *= inv;

        float* rp = out + 2 * D_SZ + (size_t)m * NEXP;
        *(float4*)rp       = make_float4(p[0], p[1], p[2], p[3]);
        *(float4*)(rp + 4) = make_float4(p[4], p[5], p[6], p[7]);

        // prob sums for aux loss, spread over 64 buckets
        float* pa = &g_paux[(m & 63) * NEXP];
#pragma unroll
        for (int i = 0; i < NEXP; i++) atomicAdd(&pa[i], p[i]);

        int i1 = 0;
#pragma unroll
        for (int i = 1; i < NEXP; i++) if (p[i] > p[i1]) i1 = i;
        int i2 = -1;
#pragma unroll
        for (int i = 0; i < NEXP; i++) {
            if (i == i1) continue;
            if (i2 < 0 || p[i] > p[i2]) i2 = i;
        }
        float denom = p[i1] + p[i2];

        size_t base = (size_t)m * NEXP * CAP;
        out[base + (size_t)i1 * CAP] = 1.0f;
        out[base + (size_t)i2 * CAP] = 1.0f;
        out[D_SZ + base + (size_t)i1 * CAP] = p[i1] / denom;
        out[D_SZ + base + (size_t)i2 * CAP] = p[i2] / denom;

        // signal completion; last block computes the aux loss
        __threadfence();
        s_last = atomicAdd(&g_done, 1u);
    }
    __syncthreads();

    if (s_last == M_TOK - 1 && tid < 64) {
        // last block: reduce g_paux[64][8] -> aux scalar (64 active threads)
        __shared__ float sr[NEXP][64];
        float4 a = ((const float4*)g_paux)[tid * 2];
        float4 b = ((const float4*)g_paux)[tid * 2 + 1];
        sr[0][tid] = a.x; sr[1][tid] = a.y; sr[2][tid] = a.z; sr[3][tid] = a.w;
        sr[4][tid] = b.x; sr[5][tid] = b.y; sr[6][tid] = b.z; sr[7][tid] = b.w;
        __syncwarp(0xFFFFFFFFu);
        // tree-reduce within 64 entries using 2 warps -> do it serially on tid 0
        if (tid == 0) {
            float aux = 0.f;
#pragma unroll
            for (int ei = 0; ei < NEXP; ei++) {
                float t = 0.f;
                for (int k = 0; k < 64; k++) t += sr[ei][k];
                float mean = t / (float)M_TOK;
                aux += mean * logf(mean * (float)NEXP + 1e-9f);
            }
            out[2 * D_SZ + (size_t)M_TOK * NEXP] = aux;
        }
    }
}

// ---------------------------------------------------------------------------
extern "C" void kernel_launch(void* const* d_in, const int* in_sizes, int n_in,
                              void* d_out, int out_size)
{
    const float* x  = (const float*)d_in[0];
    const float* w1 = (const float*)d_in[1];
    const float* b1 = (const float*)d_in[2];
    const float* w2 = (const float*)d_in[3];
    const float* b2 = (const float*)d_in[4];
    float* out = (float*)d_out;

    cudaFuncSetAttribute(gemm_fused_kernel,
                         cudaFuncAttributeMaxDynamicSharedMemorySize, SMEM_TOTAL);

    // launch 0: split fp32 -> bf16 hi/lo (+ zero g_paux, g_done)
    split_kernel<<<2560, 256>>>(x, w1);

    // launch 1: fused GEMM (+bias+ReLU -> g_h) + zero-fill of out (R8 champion)
    dim3 grid(HID / BN, M_TOK / BM);   // (8, 32)
    gemm_fused_kernel<<<grid, 256, SMEM_TOTAL>>>(b1, out);

    // launch 2: router (+ prob-sum atomics; last block computes aux loss)
    router_kernel<<<M_TOK, 256>>>(w2, b2, out);
}

// round 16
// speedup vs baseline: 1.1572x; 1.0546x over previous
#include <cuda_runtime.h>
#include <cuda_bf16.h>
#include <cstdint>
#include <math.h>

// ---------------------------------------------------------------------------
// Problem constants
// ---------------------------------------------------------------------------
#define M_TOK 4096
#define HID   1024
#define NEXP  8
#define CAP   1536
static const size_t D_SZ = (size_t)M_TOK * NEXP * CAP;   // 50,331,648 per tensor

// GEMM tiling (R8 champion structure, byte-identical main loop)
#define BM 128
#define BN 128
#define BK 64
#define KTOT 3072
#define NITER (KTOT / BK)               // 48
#define PITCHB 144                      // smem row pitch in BYTES
#define TILE_BYTES (128 * PITCHB)       // 18432
#define STAGE_BYTES (2 * TILE_BYTES)    // 36864
#define SMEM_TOTAL (3 * STAGE_BYTES)    // 110592

// ---------------------------------------------------------------------------
// Device scratch
// ---------------------------------------------------------------------------
__device__ float g_h[(size_t)M_TOK * HID];                        // 16 MB
__device__ __align__(16) __nv_bfloat16 g_Ah[(size_t)M_TOK * HID]; // 8 MB
__device__ __align__(16) __nv_bfloat16 g_Al[(size_t)M_TOK * HID]; // 8 MB
__device__ __align__(16) __nv_bfloat16 g_Bh[(size_t)HID * HID];   // 2 MB
__device__ __align__(16) __nv_bfloat16 g_Bl[(size_t)HID * HID];   // 2 MB
__device__ __align__(16) float g_paux[64 * NEXP];                 // prob sums

// ---------------------------------------------------------------------------
// PTX helpers
// ---------------------------------------------------------------------------
__device__ __forceinline__ uint32_t smem_u32(const void* p) {
    uint32_t a;
    asm("{ .reg .u64 t; cvta.to.shared.u64 t, %1; cvt.u32.u64 %0, t; }"
        : "=r"(a) : "l"(p));
    return a;
}
__device__ __forceinline__ void cp16(uint32_t dst, const void* src) {
    asm volatile("cp.async.cg.shared.global [%0], [%1], 16;"
                 :: "r"(dst), "l"(src) : "memory");
}
__device__ __forceinline__ void cp_commit() {
    asm volatile("cp.async.commit_group;" ::: "memory");
}
__device__ __forceinline__ void cp_wait1() {
    asm volatile("cp.async.wait_group 1;" ::: "memory");
}
__device__ __forceinline__ void ldsm_x4(uint32_t& r0, uint32_t& r1,
                                        uint32_t& r2, uint32_t& r3, uint32_t a) {
    asm volatile("ldmatrix.sync.aligned.m8n8.x4.shared.b16 {%0,%1,%2,%3}, [%4];"
                 : "=r"(r0), "=r"(r1), "=r"(r2), "=r"(r3) : "r"(a));
}
__device__ __forceinline__ void mma16816(float* c, const uint32_t* a,
                                         const uint32_t* b) {
    asm volatile(
        "mma.sync.aligned.m16n8k16.row.col.f32.bf16.bf16.f32 "
        "{%0,%1,%2,%3}, {%4,%5,%6,%7}, {%8,%9}, {%0,%1,%2,%3};"
        : "+f"(c[0]), "+f"(c[1]), "+f"(c[2]), "+f"(c[3])
        : "r"(a[0]), "r"(a[1]), "r"(a[2]), "r"(a[3]), "r"(b[0]), "r"(b[1]));
}

// ---------------------------------------------------------------------------
// Dummy kernel: pads launch sequence so ncu (index 3) captures the router.
// ---------------------------------------------------------------------------
__global__ void dummy_kernel() {}

// ---------------------------------------------------------------------------
// Split fp32 -> bf16 hi + lo (row-major); also zeroes g_paux.
// ---------------------------------------------------------------------------
__global__ void split_kernel(const float* __restrict__ x,
                             const float* __restrict__ w1) {
    uint32_t g = blockIdx.x * blockDim.x + threadIdx.x;   // 0..655359
    if (g < 128) ((float4*)g_paux)[g] = make_float4(0.f, 0.f, 0.f, 0.f);

    const uint32_t NA = (M_TOK * HID) / 8;                // 524288
    bool isA = g < NA;
    uint32_t gb = isA ? g : g - NA;
    const float* src = (isA ? x : w1) + (size_t)gb * 8;

    float4 v0 = *(const float4*)src;
    float4 v1 = *(const float4*)(src + 4);
    float f[8] = {v0.x, v0.y, v0.z, v0.w, v1.x, v1.y, v1.z, v1.w};

    uint32_t H[4], L[4];
#pragma unroll
    for (int i = 0; i < 4; i++) {
        __nv_bfloat16 h0 = __float2bfloat16(f[2*i]);
        __nv_bfloat16 h1 = __float2bfloat16(f[2*i+1]);
        __nv_bfloat16 l0 = __float2bfloat16(f[2*i]   - __bfloat162float(h0));
        __nv_bfloat16 l1 = __float2bfloat16(f[2*i+1] - __bfloat162float(h1));
        H[i] = (uint32_t)__bfloat16_as_ushort(h0) |
               ((uint32_t)__bfloat16_as_ushort(h1) << 16);
        L[i] = (uint32_t)__bfloat16_as_ushort(l0) |
               ((uint32_t)__bfloat16_as_ushort(l1) << 16);
    }
    if (isA) {
        *(uint4*)&g_Ah[(size_t)gb * 8] = make_uint4(H[0], H[1], H[2], H[3]);
        *(uint4*)&g_Al[(size_t)gb * 8] = make_uint4(L[0], L[1], L[2], L[3]);
    } else {
        *(uint4*)&g_Bh[(size_t)gb * 8] = make_uint4(H[0], H[1], H[2], H[3]);
        *(uint4*)&g_Bl[(size_t)gb * 8] = make_uint4(L[0], L[1], L[2], L[3]);
    }
}

// ---------------------------------------------------------------------------
// Fused HMMA GEMM (3-term bf16 split, BK=64) + interleaved zero-fill.
// BYTE-IDENTICAL to the R8 champion (141.8us config; GEMM 114.4us).
// ---------------------------------------------------------------------------
__global__ __launch_bounds__(256, 2)
void gemm_fused_kernel(const float* __restrict__ bias, float* __restrict__ out) {
    extern __shared__ __align__(128) unsigned char smem[];
    const uint32_t sb = smem_u32(smem);

    const int tid  = threadIdx.x;
    const int wid  = tid >> 5;
    const int lane = tid & 31;
    const int nb = blockIdx.x;
    const int mb = blockIdx.y;
    const int wm = wid >> 2;
    const int wn = wid & 3;

    float acc[4][4][4];
#pragma unroll
    for (int i = 0; i < 4; i++)
#pragma unroll
        for (int j = 0; j < 4; j++)
#pragma unroll
            for (int k = 0; k < 4; k++) acc[i][j][k] = 0.f;

    auto issue_stage = [&](int kt_idx) {
        int kk = kt_idx * BK;               // global k in [0, 3072)
        int p  = kk >> 10;
        int kbase = kk & 1023;
        const __nv_bfloat16* sA = (p < 2) ? g_Ah : g_Al;
        const __nv_bfloat16* sB = (p == 1) ? g_Bl : g_Bh;
        uint32_t st = sb + (kt_idx % 3) * STAGE_BYTES;
#pragma unroll
        for (int it = 0; it < 4; it++) {
            int idx = tid + it * 256;       // 0..1023
            int row = idx >> 3;             // 0..127
            int ch  = idx & 7;              // 0..7 (16B chunks)
            cp16(st + row * PITCHB + ch * 16,
                 sA + (size_t)(mb * BM + row) * HID + kbase + ch * 8);
            cp16(st + TILE_BYTES + row * PITCHB + ch * 16,
                 sB + (size_t)(nb * BN + row) * HID + kbase + ch * 8);
        }
    };

    issue_stage(0); cp_commit();
    issue_stage(1); cp_commit();

    const uint32_t gtid = (uint32_t)(mb * 8 + nb) * 256u + tid;
    float4* o4 = (float4*)out;
    const float4 zf = make_float4(0.f, 0.f, 0.f, 0.f);

    const uint32_t a_lrow = wm * 64 + (lane & 15);
    const uint32_t a_lcol = (lane >> 4) * 8;
    const uint32_t b_q = lane >> 3, b_r = lane & 7;
    const uint32_t b_nloc = wn * 32 + (b_q >> 1) * 8 + b_r;
    const uint32_t b_kloc = (b_q & 1) * 8;

    for (int i = 0; i < NITER; i++) {
        cp_wait1();
        __syncthreads();

        if (i + 2 < NITER) issue_stage(i + 2);
        cp_commit();

        // interleaved zero-fill: 8 float4 per thread per iter
#pragma unroll
        for (int j = 0; j < 8; j++)
            o4[(size_t)(i * 8 + j) * 65536u + gtid] = zf;

        uint32_t stA = sb + (i % 3) * STAGE_BYTES;
        uint32_t stB = stA + TILE_BYTES;

#pragma unroll
        for (int kt = 0; kt < 4; kt++) {
            uint32_t af[4][4];
#pragma unroll
            for (int mt = 0; mt < 4; mt++) {
                uint32_t addr = stA + (mt * 16 + a_lrow) * PITCHB
                              + (kt * 16 + a_lcol) * 2;
                ldsm_x4(af[mt][0], af[mt][1], af[mt][2], af[mt][3], addr);
            }
            uint32_t bf[4][2];
#pragma unroll
            for (int g = 0; g < 2; g++) {
                uint32_t addr = stB + (b_nloc + g * 16) * PITCHB
                              + (kt * 16 + b_kloc) * 2;
                uint32_t r0, r1, r2, r3;
                ldsm_x4(r0, r1, r2, r3, addr);
                bf[g * 2 + 0][0] = r0; bf[g * 2 + 0][1] = r1;
                bf[g * 2 + 1][0] = r2; bf[g * 2 + 1][1] = r3;
            }
#pragma unroll
            for (int mt = 0; mt < 4; mt++)
#pragma unroll
                for (int nt = 0; nt < 4; nt++)
                    mma16816(acc[mt][nt], af[mt], bf[nt]);
        }
    }

    // epilogue: bias + relu -> g_h
    const int row_base = mb * BM + wm * 64 + (lane >> 2);
    const int col_base = nb * BN + wn * 32 + (lane & 3) * 2;
#pragma unroll
    for (int nt = 0; nt < 4; nt++) {
        int c = col_base + nt * 8;
        float b0 = __ldg(&bias[c]), b1 = __ldg(&bias[c + 1]);
#pragma unroll
        for (int mt = 0; mt < 4; mt++) {
            int r = row_base + mt * 16;
            float2 v0, v1;
            v0.x = fmaxf(acc[mt][nt][0] + b0, 0.f);
            v0.y = fmaxf(acc[mt][nt][1] + b1, 0.f);
            v1.x = fmaxf(acc[mt][nt][2] + b0, 0.f);
            v1.y = fmaxf(acc[mt][nt][3] + b1, 0.f);
            *(float2*)&g_h[(size_t)r * HID + c]       = v0;
            *(float2*)&g_h[(size_t)(r + 8) * HID + c] = v1;
        }
    }
}

// ---------------------------------------------------------------------------
// Router v3: warp-per-token, w2 cached in smem once per block.
// 512 blocks x 8 warps; warp w handles token blockIdx.x*8 + w fully in
// parallel (no serial token loop, no inter-warp sync after the w2 load).
// Same dot/reduction order as the grid-4096 router -> bitwise-same logits.
// ---------------------------------------------------------------------------
__global__ __launch_bounds__(256)
void router_kernel(const float* __restrict__ w2,
                   const float* __restrict__ b2,
                   float* __restrict__ out) {
    const int tid  = threadIdx.x;
    const int wid  = tid >> 5;
    const int lane = tid & 31;

    __shared__ __align__(16) float w2s[NEXP * HID];   // 32 KB

    // load w2 once: 8192 floats = 256 threads x 8 float4
#pragma unroll
    for (int i = 0; i < 8; i++)
        ((float4*)w2s)[tid + i * 256] = ((const float4*)w2)[tid + i * 256];
    __syncthreads();

    const int m = blockIdx.x * 8 + wid;

    // load h row into registers: 8 float4 per lane (pattern lane + i*32)
    float4 a[8];
    const float4* hrow = (const float4*)&g_h[(size_t)m * HID];
#pragma unroll
    for (int i = 0; i < 8; i++) a[i] = hrow[lane + i * 32];

    // 8 expert dots from smem; full-warp xor reduction (all lanes get sum)
    const float4* w2s4 = (const float4*)w2s;
    float l[NEXP];
#pragma unroll
    for (int e = 0; e < NEXP; e++) {
        float s = 0.f;
#pragma unroll
        for (int i = 0; i < 8; i++) {
            float4 b = w2s4[e * 256 + lane + i * 32];
            s += a[i].x * b.x + a[i].y * b.y + a[i].z * b.z + a[i].w * b.w;
        }
#pragma unroll
        for (int off = 16; off > 0; off >>= 1)
            s += __shfl_xor_sync(0xFFFFFFFFu, s, off);
        l[e] = s + __ldg(&b2[e]);
    }

    if (lane == 0) {
        float p[NEXP];
        float mx = -1e30f;
#pragma unroll
        for (int i = 0; i < NEXP; i++) mx = fmaxf(mx, l[i]);
        float s = 0.f;
#pragma unroll
        for (int i = 0; i < NEXP; i++) { p[i] = expf(l[i] - mx); s += p[i]; }
        float inv = 1.f / s;
#pragma unroll
        for (int i = 0; i < NEXP; i++) p[i] *= inv;

        float* rp = out + 2 * D_SZ + (size_t)m * NEXP;
        *(float4*)rp       = make_float4(p[0], p[1], p[2], p[3]);
        *(float4*)(rp + 4) = make_float4(p[4], p[5], p[6], p[7]);

        // prob sums for aux loss, spread over 64 buckets
        float* pa = &g_paux[(m & 63) * NEXP];
#pragma unroll
        for (int i = 0; i < NEXP; i++) atomicAdd(&pa[i], p[i]);

        // top-2 (strict >, lowest index wins ties = jax.lax.top_k)
        int i1 = 0;
#pragma unroll
        for (int i = 1; i < NEXP; i++) if (p[i] > p[i1]) i1 = i;
        int i2 = -1;
#pragma unroll
        for (int i = 0; i < NEXP; i++) {
            if (i == i1) continue;
            if (i2 < 0 || p[i] > p[i2]) i2 = i;
        }
        float denom = p[i1] + p[i2];

        size_t base = (size_t)m * NEXP * CAP;
        out[base + (size_t)i1 * CAP] = 1.0f;
        out[base + (size_t)i2 * CAP] = 1.0f;
        out[D_SZ + base + (size_t)i1 * CAP] = p[i1] / denom;
        out[D_SZ + base + (size_t)i2 * CAP] = p[i2] / denom;
    }
}

// ---------------------------------------------------------------------------
// Aux finalize: reduce g_paux[64][8] -> aux loss scalar.
// ---------------------------------------------------------------------------
__global__ void aux_final_kernel(float* __restrict__ out) {
    __shared__ float s[NEXP][64];
    int tid = threadIdx.x;   // 64 threads
    float4 a = ((const float4*)g_paux)[tid * 2];
    float4 b = ((const float4*)g_paux)[tid * 2 + 1];
    s[0][tid] = a.x; s[1][tid] = a.y; s[2][tid] = a.z; s[3][tid] = a.w;
    s[4][tid] = b.x; s[5][tid] = b.y; s[6][tid] = b.z; s[7][tid] = b.w;
    __syncthreads();
    for (int str = 32; str > 0; str >>= 1) {
        if (tid < str) {
#pragma unroll
            for (int e = 0; e < NEXP; e++) s[e][tid] += s[e][tid + str];
        }
        __syncthreads();
    }
    if (tid == 0) {
        float aux = 0.f;
#pragma unroll
        for (int i = 0; i < NEXP; i++) {
            float mean = s[i][0] / (float)M_TOK;
            aux += mean * logf(mean * (float)NEXP + 1e-9f);
        }
        out[2 * D_SZ + (size_t)M_TOK * NEXP] = aux;
    }
}

// ---------------------------------------------------------------------------
extern "C" void kernel_launch(void* const* d_in, const int* in_sizes, int n_in,
                              void* d_out, int out_size)
{
    const float* x  = (const float*)d_in[0];
    const float* w1 = (const float*)d_in[1];
    const float* b1 = (const float*)d_in[2];
    const float* w2 = (const float*)d_in[3];
    const float* b2 = (const float*)d_in[4];
    float* out = (float*)d_out;

    cudaFuncSetAttribute(gemm_fused_kernel,
                         cudaFuncAttributeMaxDynamicSharedMemorySize, SMEM_TOTAL);

    // launch 0: split fp32 -> bf16 hi/lo (+ zero g_paux)
    split_kernel<<<2560, 256>>>(x, w1);

    // launch 1: fused GEMM (+bias+ReLU -> g_h) + zero-fill of out (R8 champion)
    dim3 grid(HID / BN, M_TOK / BM);   // (8, 32)
    gemm_fused_kernel<<<grid, 256, SMEM_TOTAL>>>(b1, out);

    // launch 2: padding so ncu (index 3) profiles the new router
    dummy_kernel<<<1, 32>>>();

    // launch 3: router v3 (warp-per-token, smem w2, + prob-sum atomics)
    router_kernel<<<M_TOK / 8, 256>>>(w2, b2, out);

    // launch 4: aux finalize
    aux_final_kernel<<<1, 64>>>(out);
}

// round 17
// speedup vs baseline: 1.1835x; 1.0227x over previous
#include <cuda_runtime.h>
#include <cuda_bf16.h>
#include <cstdint>
#include <math.h>

// ---------------------------------------------------------------------------
// Problem constants
// ---------------------------------------------------------------------------
#define M_TOK 4096
#define HID   1024
#define NEXP  8
#define CAP   1536
static const size_t D_SZ = (size_t)M_TOK * NEXP * CAP;   // 50,331,648 per tensor

// GEMM tiling (R8 champion structure, byte-identical main loop)
#define BM 128
#define BN 128
#define BK 64
#define KTOT 3072
#define NITER (KTOT / BK)               // 48
#define PITCHB 144                      // smem row pitch in BYTES
#define TILE_BYTES (128 * PITCHB)       // 18432
#define STAGE_BYTES (2 * TILE_BYTES)    // 36864
#define SMEM_TOTAL (3 * STAGE_BYTES)    // 110592

// ---------------------------------------------------------------------------
// Device scratch
// ---------------------------------------------------------------------------
__device__ float g_h[(size_t)M_TOK * HID];                        // 16 MB
__device__ __align__(16) __nv_bfloat16 g_Ah[(size_t)M_TOK * HID]; // 8 MB
__device__ __align__(16) __nv_bfloat16 g_Al[(size_t)M_TOK * HID]; // 8 MB
__device__ __align__(16) __nv_bfloat16 g_Bh[(size_t)HID * HID];   // 2 MB
__device__ __align__(16) __nv_bfloat16 g_Bl[(size_t)HID * HID];   // 2 MB
__device__ __align__(16) float g_paux[64 * NEXP];                 // prob sums

// ---------------------------------------------------------------------------
// PTX helpers
// ---------------------------------------------------------------------------
__device__ __forceinline__ uint32_t smem_u32(const void* p) {
    uint32_t a;
    asm("{ .reg .u64 t; cvta.to.shared.u64 t, %1; cvt.u32.u64 %0, t; }"
        : "=r"(a) : "l"(p));
    return a;
}
__device__ __forceinline__ void cp16(uint32_t dst, const void* src) {
    asm volatile("cp.async.cg.shared.global [%0], [%1], 16;"
                 :: "r"(dst), "l"(src) : "memory");
}
__device__ __forceinline__ void cp_commit() {
    asm volatile("cp.async.commit_group;" ::: "memory");
}
__device__ __forceinline__ void cp_wait1() {
    asm volatile("cp.async.wait_group 1;" ::: "memory");
}
__device__ __forceinline__ void ldsm_x4(uint32_t& r0, uint32_t& r1,
                                        uint32_t& r2, uint32_t& r3, uint32_t a) {
    asm volatile("ldmatrix.sync.aligned.m8n8.x4.shared.b16 {%0,%1,%2,%3}, [%4];"
                 : "=r"(r0), "=r"(r1), "=r"(r2), "=r"(r3) : "r"(a));
}
__device__ __forceinline__ void mma16816(float* c, const uint32_t* a,
                                         const uint32_t* b) {
    asm volatile(
        "mma.sync.aligned.m16n8k16.row.col.f32.bf16.bf16.f32 "
        "{%0,%1,%2,%3}, {%4,%5,%6,%7}, {%8,%9}, {%0,%1,%2,%3};"
        : "+f"(c[0]), "+f"(c[1]), "+f"(c[2]), "+f"(c[3])
        : "r"(a[0]), "r"(a[1]), "r"(a[2]), "r"(a[3]), "r"(b[0]), "r"(b[1]));
}

// ---------------------------------------------------------------------------
// Split fp32 -> bf16 hi + lo (row-major); also zeroes g_paux.
// ---------------------------------------------------------------------------
__global__ void split_kernel(const float* __restrict__ x,
                             const float* __restrict__ w1) {
    uint32_t g = blockIdx.x * blockDim.x + threadIdx.x;   // 0..655359
    if (g < 128) ((float4*)g_paux)[g] = make_float4(0.f, 0.f, 0.f, 0.f);

    const uint32_t NA = (M_TOK * HID) / 8;                // 524288
    bool isA = g < NA;
    uint32_t gb = isA ? g : g - NA;
    const float* src = (isA ? x : w1) + (size_t)gb * 8;

    float4 v0 = *(const float4*)src;
    float4 v1 = *(const float4*)(src + 4);
    float f[8] = {v0.x, v0.y, v0.z, v0.w, v1.x, v1.y, v1.z, v1.w};

    uint32_t H[4], L[4];
#pragma unroll
    for (int i = 0; i < 4; i++) {
        __nv_bfloat16 h0 = __float2bfloat16(f[2*i]);
        __nv_bfloat16 h1 = __float2bfloat16(f[2*i+1]);
        __nv_bfloat16 l0 = __float2bfloat16(f[2*i]   - __bfloat162float(h0));
        __nv_bfloat16 l1 = __float2bfloat16(f[2*i+1] - __bfloat162float(h1));
        H[i] = (uint32_t)__bfloat16_as_ushort(h0) |
               ((uint32_t)__bfloat16_as_ushort(h1) << 16);
        L[i] = (uint32_t)__bfloat16_as_ushort(l0) |
               ((uint32_t)__bfloat16_as_ushort(l1) << 16);
    }
    if (isA) {
        *(uint4*)&g_Ah[(size_t)gb * 8] = make_uint4(H[0], H[1], H[2], H[3]);
        *(uint4*)&g_Al[(size_t)gb * 8] = make_uint4(L[0], L[1], L[2], L[3]);
    } else {
        *(uint4*)&g_Bh[(size_t)gb * 8] = make_uint4(H[0], H[1], H[2], H[3]);
        *(uint4*)&g_Bl[(size_t)gb * 8] = make_uint4(L[0], L[1], L[2], L[3]);
    }
}

// ---------------------------------------------------------------------------
// Fused HMMA GEMM (3-term bf16 split, BK=64) + interleaved zero-fill.
// BYTE-IDENTICAL to the R8 champion main loop (GEMM 114.4us).
// ---------------------------------------------------------------------------
__global__ __launch_bounds__(256, 2)
void gemm_fused_kernel(const float* __restrict__ bias, float* __restrict__ out) {
    extern __shared__ __align__(128) unsigned char smem[];
    const uint32_t sb = smem_u32(smem);

    const int tid  = threadIdx.x;
    const int wid  = tid >> 5;
    const int lane = tid & 31;
    const int nb = blockIdx.x;
    const int mb = blockIdx.y;
    const int wm = wid >> 2;
    const int wn = wid & 3;

    float acc[4][4][4];
#pragma unroll
    for (int i = 0; i < 4; i++)
#pragma unroll
        for (int j = 0; j < 4; j++)
#pragma unroll
            for (int k = 0; k < 4; k++) acc[i][j][k] = 0.f;

    auto issue_stage = [&](int kt_idx) {
        int kk = kt_idx * BK;               // global k in [0, 3072)
        int p  = kk >> 10;
        int kbase = kk & 1023;
        const __nv_bfloat16* sA = (p < 2) ? g_Ah : g_Al;
        const __nv_bfloat16* sB = (p == 1) ? g_Bl : g_Bh;
        uint32_t st = sb + (kt_idx % 3) * STAGE_BYTES;
#pragma unroll
        for (int it = 0; it < 4; it++) {
            int idx = tid + it * 256;       // 0..1023
            int row = idx >> 3;             // 0..127
            int ch  = idx & 7;              // 0..7 (16B chunks)
            cp16(st + row * PITCHB + ch * 16,
                 sA + (size_t)(mb * BM + row) * HID + kbase + ch * 8);
            cp16(st + TILE_BYTES + row * PITCHB + ch * 16,
                 sB + (size_t)(nb * BN + row) * HID + kbase + ch * 8);
        }
    };

    issue_stage(0); cp_commit();
    issue_stage(1); cp_commit();

    const uint32_t gtid = (uint32_t)(mb * 8 + nb) * 256u + tid;
    float4* o4 = (float4*)out;
    const float4 zf = make_float4(0.f, 0.f, 0.f, 0.f);

    const uint32_t a_lrow = wm * 64 + (lane & 15);
    const uint32_t a_lcol = (lane >> 4) * 8;
    const uint32_t b_q = lane >> 3, b_r = lane & 7;
    const uint32_t b_nloc = wn * 32 + (b_q >> 1) * 8 + b_r;
    const uint32_t b_kloc = (b_q & 1) * 8;

    for (int i = 0; i < NITER; i++) {
        cp_wait1();
        __syncthreads();

        if (i + 2 < NITER) issue_stage(i + 2);
        cp_commit();

        // interleaved zero-fill: 8 float4 per thread per iter
#pragma unroll
        for (int j = 0; j < 8; j++)
            o4[(size_t)(i * 8 + j) * 65536u + gtid] = zf;

        uint32_t stA = sb + (i % 3) * STAGE_BYTES;
        uint32_t stB = stA + TILE_BYTES;

#pragma unroll
        for (int kt = 0; kt < 4; kt++) {
            uint32_t af[4][4];
#pragma unroll
            for (int mt = 0; mt < 4; mt++) {
                uint32_t addr = stA + (mt * 16 + a_lrow) * PITCHB
                              + (kt * 16 + a_lcol) * 2;
                ldsm_x4(af[mt][0], af[mt][1], af[mt][2], af[mt][3], addr);
            }
            uint32_t bf[4][2];
#pragma unroll
            for (int g = 0; g < 2; g++) {
                uint32_t addr = stB + (b_nloc + g * 16) * PITCHB
                              + (kt * 16 + b_kloc) * 2;
                uint32_t r0, r1, r2, r3;
                ldsm_x4(r0, r1, r2, r3, addr);
                bf[g * 2 + 0][0] = r0; bf[g * 2 + 0][1] = r1;
                bf[g * 2 + 1][0] = r2; bf[g * 2 + 1][1] = r3;
            }
#pragma unroll
            for (int mt = 0; mt < 4; mt++)
#pragma unroll
                for (int nt = 0; nt < 4; nt++)
                    mma16816(acc[mt][nt], af[mt], bf[nt]);
        }
    }

    // epilogue: bias + relu -> g_h
    const int row_base = mb * BM + wm * 64 + (lane >> 2);
    const int col_base = nb * BN + wn * 32 + (lane & 3) * 2;
#pragma unroll
    for (int nt = 0; nt < 4; nt++) {
        int c = col_base + nt * 8;
        float b0 = __ldg(&bias[c]), b1 = __ldg(&bias[c + 1]);
#pragma unroll
        for (int mt = 0; mt < 4; mt++) {
            int r = row_base + mt * 16;
            float2 v0, v1;
            v0.x = fmaxf(acc[mt][nt][0] + b0, 0.f);
            v0.y = fmaxf(acc[mt][nt][1] + b1, 0.f);
            v1.x = fmaxf(acc[mt][nt][2] + b0, 0.f);
            v1.y = fmaxf(acc[mt][nt][3] + b1, 0.f);
            *(float2*)&g_h[(size_t)r * HID + c]       = v0;
            *(float2*)&g_h[(size_t)(r + 8) * HID + c] = v1;
        }
    }
}

// ---------------------------------------------------------------------------
// Router v4: TWO tokens per warp (doubled ILP), w2 cached in smem per block.
// 256 blocks x 8 warps x 2 tokens. Both h rows loaded up front (16 LDG.128
// in flight); the two dot chains interleave to hide shuffle/ALU latency.
// Dot and reduction order per token identical to v3 -> same logits.
// ---------------------------------------------------------------------------
__global__ __launch_bounds__(256)
void router_kernel(const float* __restrict__ w2,
                   const float* __restrict__ b2,
                   float* __restrict__ out) {
    const int tid  = threadIdx.x;
    const int wid  = tid >> 5;
    const int lane = tid & 31;

    __shared__ __align__(16) float w2s[NEXP * HID];   // 32 KB

    // load w2 once: 8192 floats = 256 threads x 8 float4
#pragma unroll
    for (int i = 0; i < 8; i++)
        ((float4*)w2s)[tid + i * 256] = ((const float4*)w2)[tid + i * 256];
    __syncthreads();

    const int m0 = blockIdx.x * 16 + wid * 2;   // this warp's two tokens

    // load both h rows (16 independent LDG.128)
    float4 a0[8], a1[8];
    const float4* hrow0 = (const float4*)&g_h[(size_t)m0 * HID];
    const float4* hrow1 = (const float4*)&g_h[(size_t)(m0 + 1) * HID];
#pragma unroll
    for (int i = 0; i < 8; i++) a0[i] = hrow0[lane + i * 32];
#pragma unroll
    for (int i = 0; i < 8; i++) a1[i] = hrow1[lane + i * 32];

    const float4* w2s4 = (const float4*)w2s;
    float l0[NEXP], l1[NEXP];
#pragma unroll
    for (int e = 0; e < NEXP; e++) {
        float s0 = 0.f, s1 = 0.f;
#pragma unroll
        for (int i = 0; i < 8; i++) {
            float4 b = w2s4[e * 256 + lane + i * 32];
            s0 += a0[i].x * b.x + a0[i].y * b.y + a0[i].z * b.z + a0[i].w * b.w;
            s1 += a1[i].x * b.x + a1[i].y * b.y + a1[i].z * b.z + a1[i].w * b.w;
        }
#pragma unroll
        for (int off = 16; off > 0; off >>= 1) {
            s0 += __shfl_xor_sync(0xFFFFFFFFu, s0, off);
            s1 += __shfl_xor_sync(0xFFFFFFFFu, s1, off);
        }
        float be = __ldg(&b2[e]);
        l0[e] = s0 + be;
        l1[e] = s1 + be;
    }

    if (lane == 0) {
#pragma unroll
        for (int t = 0; t < 2; t++) {
            const int m = m0 + t;
            float p[NEXP];
            float mx = -1e30f;
#pragma unroll
            for (int i = 0; i < NEXP; i++) {
                float v = t ? l1[i] : l0[i];
                p[i] = v;
                mx = fmaxf(mx, v);
            }
            float s = 0.f;
#pragma unroll
            for (int i = 0; i < NEXP; i++) { p[i] = expf(p[i] - mx); s += p[i]; }
            float inv = 1.f / s;
#pragma unroll
            for (int i = 0; i < NEXP; i++) p[i] *= inv;

            float* rp = out + 2 * D_SZ + (size_t)m * NEXP;
            *(float4*)rp       = make_float4(p[0], p[1], p[2], p[3]);
            *(float4*)(rp + 4) = make_float4(p[4], p[5], p[6], p[7]);

            // prob sums for aux loss, spread over 64 buckets
            float* pa = &g_paux[(m & 63) * NEXP];
#pragma unroll
            for (int i = 0; i < NEXP; i++) atomicAdd(&pa[i], p[i]);

            // top-2 (strict >, lowest index wins ties = jax.lax.top_k)
            int i1 = 0;
#pragma unroll
            for (int i = 1; i < NEXP; i++) if (p[i] > p[i1]) i1 = i;
            int i2 = -1;
#pragma unroll
            for (int i = 0; i < NEXP; i++) {
                if (i == i1) continue;
                if (i2 < 0 || p[i] > p[i2]) i2 = i;
            }
            float denom = p[i1] + p[i2];

            size_t base = (size_t)m * NEXP * CAP;
            out[base + (size_t)i1 * CAP] = 1.0f;
            out[base + (size_t)i2 * CAP] = 1.0f;
            out[D_SZ + base + (size_t)i1 * CAP] = p[i1] / denom;
            out[D_SZ + base + (size_t)i2 * CAP] = p[i2] / denom;
        }
    }
}

// ---------------------------------------------------------------------------
// Aux finalize: reduce g_paux[64][8] -> aux loss scalar.
// ---------------------------------------------------------------------------
__global__ void aux_final_kernel(float* __restrict__ out) {
    __shared__ float s[NEXP][64];
    int tid = threadIdx.x;   // 64 threads
    float4 a = ((const float4*)g_paux)[tid * 2];
    float4 b = ((const float4*)g_paux)[tid * 2 + 1];
    s[0][tid] = a.x; s[1][tid] = a.y; s[2][tid] = a.z; s[3][tid] = a.w;
    s[4][tid] = b.x; s[5][tid] = b.y; s[6][tid] = b.z; s[7][tid] = b.w;
    __syncthreads();
    for (int str = 32; str > 0; str >>= 1) {
        if (tid < str) {
#pragma unroll
            for (int e = 0; e < NEXP; e++) s[e][tid] += s[e][tid + str];
        }
        __syncthreads();
    }
    if (tid == 0) {
        float aux = 0.f;
#pragma unroll
        for (int i = 0; i < NEXP; i++) {
            float mean = s[i][0] / (float)M_TOK;
            aux += mean * logf(mean * (float)NEXP + 1e-9f);
        }
        out[2 * D_SZ + (size_t)M_TOK * NEXP] = aux;
    }
}

// ---------------------------------------------------------------------------
extern "C" void kernel_launch(void* const* d_in, const int* in_sizes, int n_in,
                              void* d_out, int out_size)
{
    const float* x  = (const float*)d_in[0];
    const float* w1 = (const float*)d_in[1];
    const float* b1 = (const float*)d_in[2];
    const float* w2 = (const float*)d_in[3];
    const float* b2 = (const float*)d_in[4];
    float* out = (float*)d_out;

    cudaFuncSetAttribute(gemm_fused_kernel,
                         cudaFuncAttributeMaxDynamicSharedMemorySize, SMEM_TOTAL);

    // launch 0: split fp32 -> bf16 hi/lo (+ zero g_paux)
    split_kernel<<<2560, 256>>>(x, w1);

    // launch 1: fused GEMM (+bias+ReLU -> g_h) + zero-fill of out
    dim3 grid(HID / BN, M_TOK / BM);   // (8, 32)
    gemm_fused_kernel<<<grid, 256, SMEM_TOTAL>>>(b1, out);

    // launch 2: router v4 (2 tokens/warp, smem w2, + prob-sum atomics)
    router_kernel<<<M_TOK / 16, 256>>>(w2, b2, out);

    // launch 3: aux finalize
    aux_final_kernel<<<1, 64>>>(out);
}